// round 1
// baseline (speedup 1.0000x reference)
#include <cuda_runtime.h>
#include <math_constants.h>
#include <cfloat>

#define B   32
#define C   512
#define H   56
#define W   56
#define HW  (H * W)          // 3136
#define KD  768
#define NTOT ((size_t)B * C * HW)

// Scratch (alloc-free rule: __device__ globals)
__device__ float g_pooled[B * 2 * HW];   // [B][2][HW]: ch0=max, ch1=mean
__device__ float g_scale[B * HW];        // sigmoid(attention)
__device__ float g_bias[B];              // keyword @ proj_w.T + proj_b

// ---------------------------------------------------------------------------
// Kernel 1: channel max + mean pooling. One thread per (b, hw).
// Lanes within a warp cover consecutive hw -> each channel load is a
// coalesced 128B line. Unroll 8 for MLP.
// ---------------------------------------------------------------------------
__global__ void pool_kernel(const float* __restrict__ x) {
    int idx = blockIdx.x * blockDim.x + threadIdx.x;   // b*HW + hw
    if (idx >= B * HW) return;
    int b  = idx / HW;
    int hw = idx - b * HW;

    const float* p = x + (size_t)b * C * HW + hw;
    float mx  = -FLT_MAX;
    float sum = 0.0f;
#pragma unroll 8
    for (int c = 0; c < C; ++c) {
        float v = __ldg(p + (size_t)c * HW);
        mx  = fmaxf(mx, v);
        sum += v;
    }
    g_pooled[b * 2 * HW + hw]      = mx;
    g_pooled[b * 2 * HW + HW + hw] = sum * (1.0f / C);
}

// ---------------------------------------------------------------------------
// Kernel 2: keyword bias. One block per batch, 256 threads reduce KD=768.
// ---------------------------------------------------------------------------
__global__ void bias_kernel(const float* __restrict__ keyword,
                            const float* __restrict__ proj_w,
                            const float* __restrict__ proj_b) {
    int b = blockIdx.x;
    int tid = threadIdx.x;
    float s = 0.0f;
    for (int k = tid; k < KD; k += blockDim.x)
        s += keyword[b * KD + k] * proj_w[k];

    // warp reduce
#pragma unroll
    for (int off = 16; off > 0; off >>= 1)
        s += __shfl_down_sync(0xFFFFFFFFu, s, off);

    __shared__ float sm[8];
    if ((tid & 31) == 0) sm[tid >> 5] = s;
    __syncthreads();
    if (tid == 0) {
        float t = 0.0f;
        int nw = blockDim.x >> 5;
        for (int i = 0; i < nw; ++i) t += sm[i];
        g_bias[b] = t + proj_b[0];
    }
}

// ---------------------------------------------------------------------------
// Kernel 3: 7x7 conv (2 -> 1 ch, SAME pad=3) + conv_b + keyword bias + sigmoid.
// One thread per (b, hw). Pooled map (803 KB) is L2-resident; conv_w (98
// floats) hits L1 constants. Tiny kernel.
// ---------------------------------------------------------------------------
__global__ void conv_kernel(const float* __restrict__ conv_w,
                            const float* __restrict__ conv_b) {
    int idx = blockIdx.x * blockDim.x + threadIdx.x;
    if (idx >= B * HW) return;
    int b  = idx / HW;
    int hw = idx - b * HW;
    int h  = hw / W;
    int w  = hw - h * W;

    float acc = conv_b[0] + g_bias[b];

    const float* pb = g_pooled + b * 2 * HW;
#pragma unroll
    for (int ci = 0; ci < 2; ++ci) {
        const float* pc = pb + ci * HW;
        const float* wc = conv_w + ci * 49;
#pragma unroll
        for (int kh = 0; kh < 7; ++kh) {
            int hh = h + kh - 3;
            if ((unsigned)hh >= (unsigned)H) continue;
#pragma unroll
            for (int kw = 0; kw < 7; ++kw) {
                int ww = w + kw - 3;
                if ((unsigned)ww >= (unsigned)W) continue;
                acc += pc[hh * W + ww] * __ldg(wc + kh * 7 + kw);
            }
        }
    }
    // sigmoid
    g_scale[idx] = 1.0f / (1.0f + __expf(-acc));
}

// ---------------------------------------------------------------------------
// Kernel 4: out = x * scale (broadcast over C). float4 streaming.
// scale (401 KB) stays L2-resident, so effective traffic is read-x + write-out.
// ---------------------------------------------------------------------------
__global__ void mul_kernel(const float4* __restrict__ x4,
                           float4* __restrict__ out4) {
    const int HW4  = HW / 4;          // 784
    const int CHW4 = C * HW4;         // per-batch float4 count
    int i = blockIdx.x * blockDim.x + threadIdx.x;
    if (i >= (int)(NTOT / 4)) return;

    int b   = i / CHW4;
    int rem = i - b * CHW4;
    int hw4 = rem % HW4;

    float4 s = reinterpret_cast<const float4*>(g_scale)[b * HW4 + hw4];
    float4 v = x4[i];
    v.x *= s.x; v.y *= s.y; v.z *= s.z; v.w *= s.w;
    out4[i] = v;
}

// ---------------------------------------------------------------------------
extern "C" void kernel_launch(void* const* d_in, const int* in_sizes, int n_in,
                              void* d_out, int out_size) {
    const float* x       = (const float*)d_in[0];
    const float* keyword = (const float*)d_in[1];
    const float* conv_w  = (const float*)d_in[2];
    const float* conv_b  = (const float*)d_in[3];
    const float* proj_w  = (const float*)d_in[4];
    const float* proj_b  = (const float*)d_in[5];
    float* out = (float*)d_out;

    // 1) pooling over channels
    {
        int n = B * HW;
        int threads = 256;
        pool_kernel<<<(n + threads - 1) / threads, threads>>>(x);
    }
    // 2) keyword bias (independent of 1; small)
    bias_kernel<<<B, 256>>>(keyword, proj_w, proj_b);
    // 3) conv + sigmoid -> scale
    {
        int n = B * HW;
        int threads = 256;
        conv_kernel<<<(n + threads - 1) / threads, threads>>>(conv_w, conv_b);
    }
    // 4) gate multiply
    {
        int n4 = (int)(NTOT / 4);
        int threads = 256;
        mul_kernel<<<(n4 + threads - 1) / threads, threads>>>(
            (const float4*)x, (float4*)out);
    }
}

// round 2
// speedup vs baseline: 1.0737x; 1.0737x over previous
#include <cuda_runtime.h>
#include <cfloat>

#define B   32
#define C   512
#define H   56
#define W   56
#define HW  (H * W)          // 3136
#define HW4 (HW / 4)         // 784
#define KD  768
#define CSPLIT 8
#define CCHUNK (C / CSPLIT)  // 64
#define NB4 (B * HW4)        // 25088
#define NTOT ((size_t)B * C * HW)

// Scratch (alloc-free rule: __device__ globals)
__device__ float4 g_pmax[CSPLIT * NB4];  // per-chunk partial max
__device__ float4 g_psum[CSPLIT * NB4];  // per-chunk partial sum
__device__ float  g_pooled[B * 2 * HW];  // [B][2][HW]: ch0=max, ch1=mean
__device__ float  g_scale[B * HW];       // sigmoid(attention)
__device__ float  g_bias[B];             // keyword @ proj_w.T + proj_b

// ---------------------------------------------------------------------------
// Kernel 1: partial channel max+sum pooling. 8-way channel split, float4
// columns. thread i -> (chunk, b, hw4); consecutive lanes hit consecutive
// hw4 -> fully coalesced 512B warp transactions. unroll 16 for deep MLP.
// ---------------------------------------------------------------------------
__global__ void pool_partial_kernel(const float4* __restrict__ x4) {
    int i = blockIdx.x * blockDim.x + threadIdx.x;
    if (i >= CSPLIT * NB4) return;
    int chunk = i / NB4;
    int r     = i - chunk * NB4;          // b*HW4 + hw4
    int b     = r / HW4;
    int hw4   = r - b * HW4;

    const float4* p = x4 + (size_t)b * C * HW4
                         + (size_t)chunk * CCHUNK * HW4 + hw4;

    float4 v0 = __ldg(p);
    float4 mx = v0;
    float4 sm = v0;
#pragma unroll 16
    for (int c = 1; c < CCHUNK; ++c) {
        float4 v = __ldg(p + (size_t)c * HW4);
        mx.x = fmaxf(mx.x, v.x); mx.y = fmaxf(mx.y, v.y);
        mx.z = fmaxf(mx.z, v.z); mx.w = fmaxf(mx.w, v.w);
        sm.x += v.x; sm.y += v.y; sm.z += v.z; sm.w += v.w;
    }
    g_pmax[i] = mx;
    g_psum[i] = sm;
}

// ---------------------------------------------------------------------------
// Kernel 2: combine 8 partials -> pooled max / mean. All L2-resident.
// ---------------------------------------------------------------------------
__global__ void combine_kernel() {
    int r = blockIdx.x * blockDim.x + threadIdx.x;   // b*HW4 + hw4
    if (r >= NB4) return;
    int b   = r / HW4;
    int hw4 = r - b * HW4;

    float4 mx = g_pmax[r];
    float4 sm = g_psum[r];
#pragma unroll
    for (int c = 1; c < CSPLIT; ++c) {
        float4 m = g_pmax[c * NB4 + r];
        float4 s = g_psum[c * NB4 + r];
        mx.x = fmaxf(mx.x, m.x); mx.y = fmaxf(mx.y, m.y);
        mx.z = fmaxf(mx.z, m.z); mx.w = fmaxf(mx.w, m.w);
        sm.x += s.x; sm.y += s.y; sm.z += s.z; sm.w += s.w;
    }
    const float inv = 1.0f / C;
    sm.x *= inv; sm.y *= inv; sm.z *= inv; sm.w *= inv;

    float4* pool4 = reinterpret_cast<float4*>(g_pooled);
    pool4[(b * 2 * HW + 0) / 4 + hw4]  = mx;   // max channel
    pool4[(b * 2 * HW + HW) / 4 + hw4] = sm;   // mean channel
}

// ---------------------------------------------------------------------------
// Kernel 3: keyword bias. One block per batch, 256 threads reduce KD=768.
// ---------------------------------------------------------------------------
__global__ void bias_kernel(const float* __restrict__ keyword,
                            const float* __restrict__ proj_w,
                            const float* __restrict__ proj_b) {
    int b = blockIdx.x;
    int tid = threadIdx.x;
    float s = 0.0f;
    for (int k = tid; k < KD; k += blockDim.x)
        s += keyword[b * KD + k] * proj_w[k];
#pragma unroll
    for (int off = 16; off > 0; off >>= 1)
        s += __shfl_down_sync(0xFFFFFFFFu, s, off);
    __shared__ float smem[8];
    if ((tid & 31) == 0) smem[tid >> 5] = s;
    __syncthreads();
    if (tid == 0) {
        float t = 0.0f;
        int nw = blockDim.x >> 5;
        for (int i = 0; i < nw; ++i) t += smem[i];
        g_bias[b] = t + proj_b[0];
    }
}

// ---------------------------------------------------------------------------
// Kernel 4: 7x7 conv (2->1 ch, SAME pad=3) + biases + sigmoid -> g_scale.
// Pooled map is L2-resident (803 KB); tiny kernel.
// ---------------------------------------------------------------------------
__global__ void conv_kernel(const float* __restrict__ conv_w,
                            const float* __restrict__ conv_b) {
    int idx = blockIdx.x * blockDim.x + threadIdx.x;
    if (idx >= B * HW) return;
    int b  = idx / HW;
    int hw = idx - b * HW;
    int h  = hw / W;
    int w  = hw - h * W;

    float acc = conv_b[0] + g_bias[b];
    const float* pb = g_pooled + b * 2 * HW;
#pragma unroll
    for (int ci = 0; ci < 2; ++ci) {
        const float* pc = pb + ci * HW;
        const float* wc = conv_w + ci * 49;
#pragma unroll
        for (int kh = 0; kh < 7; ++kh) {
            int hh = h + kh - 3;
            if ((unsigned)hh >= (unsigned)H) continue;
#pragma unroll
            for (int kw = 0; kw < 7; ++kw) {
                int ww = w + kw - 3;
                if ((unsigned)ww >= (unsigned)W) continue;
                acc += pc[hh * W + ww] * __ldg(wc + kh * 7 + kw);
            }
        }
    }
    g_scale[idx] = 1.0f / (1.0f + __expf(-acc));
}

// ---------------------------------------------------------------------------
// Kernel 5: out = x * scale (broadcast over C). float4 streaming.
// ---------------------------------------------------------------------------
__global__ void mul_kernel(const float4* __restrict__ x4,
                           float4* __restrict__ out4) {
    const int CHW4 = C * HW4;
    int i = blockIdx.x * blockDim.x + threadIdx.x;
    if (i >= (int)(NTOT / 4)) return;
    int b   = i / CHW4;
    int rem = i - b * CHW4;
    int hw4 = rem % HW4;

    float4 s = reinterpret_cast<const float4*>(g_scale)[b * HW4 + hw4];
    float4 v = x4[i];
    v.x *= s.x; v.y *= s.y; v.z *= s.z; v.w *= s.w;
    out4[i] = v;
}

// ---------------------------------------------------------------------------
extern "C" void kernel_launch(void* const* d_in, const int* in_sizes, int n_in,
                              void* d_out, int out_size) {
    const float* x       = (const float*)d_in[0];
    const float* keyword = (const float*)d_in[1];
    const float* conv_w  = (const float*)d_in[2];
    const float* conv_b  = (const float*)d_in[3];
    const float* proj_w  = (const float*)d_in[4];
    const float* proj_b  = (const float*)d_in[5];
    float* out = (float*)d_out;

    {
        int n = CSPLIT * NB4;
        pool_partial_kernel<<<(n + 255) / 256, 256>>>((const float4*)x);
    }
    bias_kernel<<<B, 256>>>(keyword, proj_w, proj_b);
    combine_kernel<<<(NB4 + 255) / 256, 256>>>();
    {
        int n = B * HW;
        conv_kernel<<<(n + 255) / 256, 256>>>(conv_w, conv_b);
    }
    {
        int n4 = (int)(NTOT / 4);
        mul_kernel<<<(n4 + 255) / 256, 256>>>((const float4*)x, (float4*)out);
    }
}

// round 3
// speedup vs baseline: 1.1733x; 1.0928x over previous
#include <cuda_runtime.h>
#include <cfloat>

#define B   32
#define C   512
#define H   56
#define W   56
#define HW  (H * W)          // 3136
#define HW4 (HW / 4)         // 784
#define KD  768
#define NTOT ((size_t)B * C * HW)

// pooling block geometry: 16 hw4-columns x 16 channel-chunks
#define PTX 16               // hw4 columns per block
#define PTY 16               // channel chunks
#define PCC (C / PTY)        // 32 channels per chunk
#define PBLK_PER_B (HW4 / PTX)   // 49

// conv tiling
#define CROWS 4              // output rows per block
#define CTH   (CROWS + 6)    // tile rows incl. halo
#define CTW   64             // padded tile width (W + 6 = 62, pad to 64)

// Scratch (alloc-free rule: __device__ globals)
__device__ float g_pooled[B * 2 * HW];  // [B][2][HW]: ch0=max, ch1=mean
__device__ float g_scale[B * HW];       // sigmoid(attention)
__device__ float g_bias[B];             // keyword @ proj_w.T + proj_b

// ---------------------------------------------------------------------------
// Kernel 1: fused channel max+mean pooling (single kernel, smem reduce).
// grid = (PBLK_PER_B, B). Each block covers 16 float4 hw-positions; thread
// (tx,ty) reduces 32 channels of column tx, then tree-reduce across ty.
// ---------------------------------------------------------------------------
__global__ void pool_kernel(const float4* __restrict__ x4) {
    int tx = threadIdx.x & (PTX - 1);
    int ty = threadIdx.x >> 4;            // 0..15 channel chunk
    int b    = blockIdx.y;
    int hw4  = blockIdx.x * PTX + tx;

    const float4* p = x4 + (size_t)b * C * HW4
                         + (size_t)ty * PCC * HW4 + hw4;
    float4 v0 = __ldcs(p);
    float4 mx = v0;
    float4 sm = v0;
#pragma unroll
    for (int c = 1; c < PCC; ++c) {
        float4 v = __ldcs(p + (size_t)c * HW4);
        mx.x = fmaxf(mx.x, v.x); mx.y = fmaxf(mx.y, v.y);
        mx.z = fmaxf(mx.z, v.z); mx.w = fmaxf(mx.w, v.w);
        sm.x += v.x; sm.y += v.y; sm.z += v.z; sm.w += v.w;
    }

    __shared__ float4 smax[PTY][PTX];
    __shared__ float4 ssum[PTY][PTX];
    smax[ty][tx] = mx;
    ssum[ty][tx] = sm;
    __syncthreads();

#pragma unroll
    for (int s = PTY / 2; s > 0; s >>= 1) {
        if (ty < s) {
            float4 m = smax[ty + s][tx];
            float4 q = ssum[ty + s][tx];
            mx.x = fmaxf(mx.x, m.x); mx.y = fmaxf(mx.y, m.y);
            mx.z = fmaxf(mx.z, m.z); mx.w = fmaxf(mx.w, m.w);
            sm.x += q.x; sm.y += q.y; sm.z += q.z; sm.w += q.w;
            smax[ty][tx] = mx;
            ssum[ty][tx] = sm;
        }
        __syncthreads();
    }

    if (ty == 0) {
        const float inv = 1.0f / C;
        sm.x *= inv; sm.y *= inv; sm.z *= inv; sm.w *= inv;
        float4* pool4 = reinterpret_cast<float4*>(g_pooled);
        pool4[(b * 2 * HW) / 4 + hw4]      = mx;  // max channel
        pool4[(b * 2 * HW + HW) / 4 + hw4] = sm;  // mean channel
    }
}

// ---------------------------------------------------------------------------
// Kernel 2: keyword bias. One block per batch, 256 threads reduce KD=768.
// ---------------------------------------------------------------------------
__global__ void bias_kernel(const float* __restrict__ keyword,
                            const float* __restrict__ proj_w,
                            const float* __restrict__ proj_b) {
    int b = blockIdx.x;
    int tid = threadIdx.x;
    float s = 0.0f;
    for (int k = tid; k < KD; k += blockDim.x)
        s += keyword[b * KD + k] * proj_w[k];
#pragma unroll
    for (int off = 16; off > 0; off >>= 1)
        s += __shfl_down_sync(0xFFFFFFFFu, s, off);
    __shared__ float smem[8];
    if ((tid & 31) == 0) smem[tid >> 5] = s;
    __syncthreads();
    if (tid == 0) {
        float t = 0.0f;
        int nw = blockDim.x >> 5;
        for (int i = 0; i < nw; ++i) t += smem[i];
        g_bias[b] = t + proj_b[0];
    }
}

// ---------------------------------------------------------------------------
// Kernel 3: 7x7 conv (2->1 ch, SAME pad=3) + biases + sigmoid -> g_scale.
// Smem-tiled: block = (b, 4-row stripe). Cooperative halo load, then each
// thread computes one output from smem. grid = (14, 32), 256 threads.
// ---------------------------------------------------------------------------
__global__ void conv_kernel(const float* __restrict__ conv_w,
                            const float* __restrict__ conv_b) {
    __shared__ float tile[2][CTH][CTW];   // 2ch x 10 x 64 = 5 KB
    __shared__ float wts[98];
    __shared__ float sbias;

    int b  = blockIdx.y;
    int r0 = blockIdx.x * CROWS;          // first output row
    int tid = threadIdx.x;

    if (tid < 98) wts[tid] = conv_w[tid];
    if (tid == 0) sbias = conv_b[0] + g_bias[b];

    // cooperative tile load: 2 * CTH * 62 valid elems, zero-padded halo
    const float* pb = g_pooled + b * 2 * HW;
    for (int i = tid; i < 2 * CTH * CTW; i += blockDim.x) {
        int ci = i / (CTH * CTW);
        int rr = (i / CTW) % CTH;
        int cc = i % CTW;
        int hh = r0 + rr - 3;
        int ww = cc - 3;
        float v = 0.0f;
        if ((unsigned)hh < (unsigned)H && (unsigned)ww < (unsigned)W)
            v = pb[ci * HW + hh * W + ww];
        tile[ci][rr][cc] = v;
    }
    __syncthreads();

    // outputs: CROWS * W = 224 per block
    if (tid < CROWS * W) {
        int r = tid / W;                  // local row 0..3
        int w = tid - r * W;              // col 0..55
        float acc = sbias;
#pragma unroll
        for (int ci = 0; ci < 2; ++ci) {
#pragma unroll
            for (int kh = 0; kh < 7; ++kh) {
#pragma unroll
                for (int kw = 0; kw < 7; ++kw) {
                    acc += tile[ci][r + kh][w + kw] * wts[ci * 49 + kh * 7 + kw];
                }
            }
        }
        g_scale[b * HW + (r0 + r) * W + w] = 1.0f / (1.0f + __expf(-acc));
    }
}

// ---------------------------------------------------------------------------
// Kernel 4: out = x * scale (broadcast over C). float4 streaming with
// streaming hints on x/out so L2 retains g_scale.
// ---------------------------------------------------------------------------
__global__ void mul_kernel(const float4* __restrict__ x4,
                           float4* __restrict__ out4) {
    const int CHW4 = C * HW4;
    int i = blockIdx.x * blockDim.x + threadIdx.x;
    if (i >= (int)(NTOT / 4)) return;
    int b   = i / CHW4;
    int rem = i - b * CHW4;
    int hw4 = rem % HW4;

    float4 s = reinterpret_cast<const float4*>(g_scale)[b * HW4 + hw4];
    float4 v = __ldcs(x4 + i);
    v.x *= s.x; v.y *= s.y; v.z *= s.z; v.w *= s.w;
    __stcs(out4 + i, v);
}

// ---------------------------------------------------------------------------
extern "C" void kernel_launch(void* const* d_in, const int* in_sizes, int n_in,
                              void* d_out, int out_size) {
    const float* x       = (const float*)d_in[0];
    const float* keyword = (const float*)d_in[1];
    const float* conv_w  = (const float*)d_in[2];
    const float* conv_b  = (const float*)d_in[3];
    const float* proj_w  = (const float*)d_in[4];
    const float* proj_b  = (const float*)d_in[5];
    float* out = (float*)d_out;

    bias_kernel<<<B, 256>>>(keyword, proj_w, proj_b);
    {
        dim3 grid(PBLK_PER_B, B);        // 49 x 32 = 1568 blocks
        pool_kernel<<<grid, PTX * PTY>>>((const float4*)x);
    }
    {
        dim3 grid(H / CROWS, B);         // 14 x 32 = 448 blocks
        conv_kernel<<<grid, 256>>>(conv_w, conv_b);
    }
    {
        int n4 = (int)(NTOT / 4);
        mul_kernel<<<(n4 + 255) / 256, 256>>>((const float4*)x, (float4*)out);
    }
}